// round 3
// baseline (speedup 1.0000x reference)
#include <cuda_runtime.h>

#define Nn 50000
#define Hh 128
#define Ee 500000
#define TK 16
#define LDP 132   // padded pitch for shared tiles
#define NBLK 196  // ceil(Nn/256)

typedef unsigned long long u64;

// Scratch (device globals: no allocation allowed)
__device__ float g_aggr[(size_t)Nn * Hh];
__device__ int   g_cnt[Nn];    // per-node degree
__device__ int   g_cur[Nn];    // fill cursors
__device__ int   g_base[Nn];   // CSR row offsets (exclusive scan of cnt)
__device__ int   g_srcs[Ee];   // bucketed source indices
__device__ int   g_bs[NBLK];   // block sums for scan

// ---------------------------------------------------------------------------
// CSR build: count -> scan -> fill
// ---------------------------------------------------------------------------
__global__ void zero_cnt_kernel() {
    int i = blockIdx.x * 256 + threadIdx.x;
    if (i < Nn) { g_cnt[i] = 0; g_cur[i] = 0; }
}

__global__ void count_kernel(const int* __restrict__ edge) {
    int e = blockIdx.x * 256 + threadIdx.x;
    if (e < Ee) atomicAdd(&g_cnt[__ldg(edge + e)], 1);
}

__device__ __forceinline__ int warp_scan_incl(int v, int lane) {
    #pragma unroll
    for (int o = 1; o < 32; o <<= 1) {
        int n = __shfl_up_sync(0xffffffffu, v, o);
        if (lane >= o) v += n;
    }
    return v;
}

__global__ void scan1_kernel() {
    __shared__ int ws[8];
    int t = threadIdx.x, lane = t & 31, wid = t >> 5;
    int i = blockIdx.x * 256 + t;
    int v = (i < Nn) ? g_cnt[i] : 0;
    int inc = warp_scan_incl(v, lane);
    if (lane == 31) ws[wid] = inc;
    __syncthreads();
    if (wid == 0) {
        int wv = (lane < 8) ? ws[lane] : 0;
        wv = warp_scan_incl(wv, lane);
        if (lane < 8) ws[lane] = wv;
    }
    __syncthreads();
    int off = (wid > 0) ? ws[wid - 1] : 0;
    if (i < Nn) g_base[i] = off + inc - v;        // exclusive within block
    if (t == 255) g_bs[blockIdx.x] = off + inc;   // block total
}

// Fixup: each block sums g_bs[0..bid-1] directly (196 ints -> trivial reduce).
__global__ void scan_fixup_kernel() {
    __shared__ int ws[8];
    __shared__ int total;
    int t = threadIdx.x, lane = t & 31, wid = t >> 5;
    int b = blockIdx.x;
    int v = (t < b) ? g_bs[t] : 0;    // NBLK=196 < 256
    #pragma unroll
    for (int o = 16; o > 0; o >>= 1) v += __shfl_xor_sync(0xffffffffu, v, o);
    if (lane == 0) ws[wid] = v;
    __syncthreads();
    if (t == 0) {
        int s = 0;
        #pragma unroll
        for (int w = 0; w < 8; w++) s += ws[w];
        total = s;
    }
    __syncthreads();
    int i = b * 256 + t;
    if (i < Nn) g_base[i] += total;
}

__global__ void fill_kernel(const int* __restrict__ edge) {
    int e = blockIdx.x * 256 + threadIdx.x;
    if (e < Ee) {
        int dst = __ldg(edge + e);        // edge_index[0][e]
        int src = __ldg(edge + Ee + e);   // edge_index[1][e]
        int pos = g_base[dst] + atomicAdd(&g_cur[dst], 1);
        g_srcs[pos] = src;
    }
}

// ---------------------------------------------------------------------------
// Gather-reduce: one warp per node, 4 floats per lane, fp32 register sums.
// Unrolled x4 for MLP.
// ---------------------------------------------------------------------------
__global__ void aggregate_kernel(const float* __restrict__ x) {
    int n = blockIdx.x * 8 + (threadIdx.x >> 5);
    if (n >= Nn) return;
    int lane = threadIdx.x & 31;
    int base = g_base[n];
    int deg  = g_cnt[n];
    float4 acc = make_float4(0.f, 0.f, 0.f, 0.f);
    int d = 0;
    for (; d + 4 <= deg; d += 4) {
        int s0 = __ldg(g_srcs + base + d);
        int s1 = __ldg(g_srcs + base + d + 1);
        int s2 = __ldg(g_srcs + base + d + 2);
        int s3 = __ldg(g_srcs + base + d + 3);
        float4 v0 = *reinterpret_cast<const float4*>(x + (size_t)s0 * Hh + lane * 4);
        float4 v1 = *reinterpret_cast<const float4*>(x + (size_t)s1 * Hh + lane * 4);
        float4 v2 = *reinterpret_cast<const float4*>(x + (size_t)s2 * Hh + lane * 4);
        float4 v3 = *reinterpret_cast<const float4*>(x + (size_t)s3 * Hh + lane * 4);
        acc.x += v0.x + v1.x + v2.x + v3.x;
        acc.y += v0.y + v1.y + v2.y + v3.y;
        acc.z += v0.z + v1.z + v2.z + v3.z;
        acc.w += v0.w + v1.w + v2.w + v3.w;
    }
    for (; d < deg; d++) {
        int src = __ldg(g_srcs + base + d);
        float4 v = *reinterpret_cast<const float4*>(x + (size_t)src * Hh + lane * 4);
        acc.x += v.x; acc.y += v.y; acc.z += v.z; acc.w += v.w;
    }
    *reinterpret_cast<float4*>(g_aggr + (size_t)n * Hh + lane * 4) = acc;
}

// ---------------------------------------------------------------------------
// f32x2 packed-FMA helpers
// ---------------------------------------------------------------------------
__device__ __forceinline__ u64 pack_dup(float v) {
    u64 r;
    asm("mov.b64 %0, {%1,%1};" : "=l"(r) : "f"(v));
    return r;
}
__device__ __forceinline__ void fma2(u64& acc, u64 a, u64 b) {
    asm("fma.rn.f32x2 %0, %1, %2, %0;" : "+l"(acc) : "l"(a), "l"(b));
}

// ---------------------------------------------------------------------------
// Fused GEMM:
//   h1   = relu( aggr @ Wl^T + x_a @ (W0+W1)^T + (bl+b0+b1) )   (per 128-row tile)
//   out  = h1 @ out_w^T + out_b
// Phase 1: classic tiled SGEMM (K=256 over 2 segments) -> acc2 registers.
// Stage relu'd h1 tile k-major into Hs (smem), then phase 2 GEMM vs out_w.
// Dynamic smem: As(16x132) + Bs(16x132) + Hs(128x132) = 84.5 KB, 2 blocks/SM.
// ---------------------------------------------------------------------------
__global__ __launch_bounds__(256, 2) void fused_gemm_kernel(
    const float* __restrict__ A0, const float* __restrict__ W0,
    const float* __restrict__ A1, const float* __restrict__ W1a,
    const float* __restrict__ W1b,
    const float* __restrict__ ba, const float* __restrict__ bb,
    const float* __restrict__ bc,
    const float* __restrict__ Wout, const float* __restrict__ bout,
    float* __restrict__ C, int M)
{
    extern __shared__ __align__(16) float smem[];
    float* As = smem;                  // TK * LDP
    float* Bs = smem + TK * LDP;       // TK * LDP
    float* Hs = smem + 2 * TK * LDP;   // 128 * LDP (k-major h1 tile)

    const int tid = threadIdx.x;
    const int ty = tid >> 4;        // 0..15
    const int tx = tid & 15;        // 0..15
    const int m0 = ty * 8;
    const int n0 = tx * 8;
    const int bm = blockIdx.x * 128;

    // acc2[p][j] = ( h1[m0+2p][n0+j], h1[m0+2p+1][n0+j] )
    u64 acc2[4][8];
    #pragma unroll
    for (int p = 0; p < 4; p++)
        #pragma unroll
        for (int j = 0; j < 8; j++) acc2[p][j] = 0ull;

    // ---------------- Phase 1: h1 pre-activation ----------------
    #pragma unroll 1
    for (int seg = 0; seg < 2; seg++) {
        const float* A  = seg ? A1 : A0;
        const float* Wa = seg ? W1a : W0;
        const float* Wb = seg ? W1b : nullptr;

        #pragma unroll 1
        for (int kk = 0; kk < 128; kk += TK) {
            #pragma unroll
            for (int q = 0; q < 2; q++) {
                int l = q * 256 + tid;     // 0..511
                int row = l >> 2;          // 0..127
                int kq = (l & 3) * 4;      // 0,4,8,12

                float4 va = make_float4(0.f, 0.f, 0.f, 0.f);
                if (bm + row < M)
                    va = *reinterpret_cast<const float4*>(
                        A + (size_t)(bm + row) * 128 + kk + kq);
                As[(kq + 0) * LDP + row] = va.x;
                As[(kq + 1) * LDP + row] = va.y;
                As[(kq + 2) * LDP + row] = va.z;
                As[(kq + 3) * LDP + row] = va.w;

                float4 vb = *reinterpret_cast<const float4*>(
                    Wa + (size_t)row * 128 + kk + kq);
                if (Wb) {
                    float4 v2 = *reinterpret_cast<const float4*>(
                        Wb + (size_t)row * 128 + kk + kq);
                    vb.x += v2.x; vb.y += v2.y; vb.z += v2.z; vb.w += v2.w;
                }
                Bs[(kq + 0) * LDP + row] = vb.x;
                Bs[(kq + 1) * LDP + row] = vb.y;
                Bs[(kq + 2) * LDP + row] = vb.z;
                Bs[(kq + 3) * LDP + row] = vb.w;
            }
            __syncthreads();

            #pragma unroll
            for (int k = 0; k < TK; k++) {
                ulonglong2 a01 = *reinterpret_cast<ulonglong2*>(&As[k * LDP + m0]);
                ulonglong2 a23 = *reinterpret_cast<ulonglong2*>(&As[k * LDP + m0 + 4]);
                u64 a2[4] = { a01.x, a01.y, a23.x, a23.y };

                float4 t0 = *reinterpret_cast<float4*>(&Bs[k * LDP + n0]);
                float4 t1 = *reinterpret_cast<float4*>(&Bs[k * LDP + n0 + 4]);
                u64 b2[8] = { pack_dup(t0.x), pack_dup(t0.y),
                              pack_dup(t0.z), pack_dup(t0.w),
                              pack_dup(t1.x), pack_dup(t1.y),
                              pack_dup(t1.z), pack_dup(t1.w) };

                #pragma unroll
                for (int p = 0; p < 4; p++)
                    #pragma unroll
                    for (int j = 0; j < 8; j++)
                        fma2(acc2[p][j], a2[p], b2[j]);
            }
            __syncthreads();
        }
    }

    // ---- bias + relu, stage h1 tile k-major into Hs (j-staggered writes) ----
    {
        float bias[8];
        #pragma unroll
        for (int j = 0; j < 8; j++)
            bias[j] = __ldg(ba + n0 + j) + __ldg(bb + n0 + j) + __ldg(bc + n0 + j);
        #pragma unroll
        for (int p = 0; p < 4; p++) {
            #pragma unroll
            for (int jj = 0; jj < 8; jj++) {
                int j = (jj + tx) & 7;   // stagger to break bank conflicts
                float2 f = *reinterpret_cast<float2*>(&acc2[p][j]);
                f.x = fmaxf(f.x + bias[j], 0.f);
                f.y = fmaxf(f.y + bias[j], 0.f);
                *reinterpret_cast<float2*>(&Hs[(n0 + j) * LDP + m0 + 2 * p]) = f;
            }
        }
    }
    __syncthreads();

    // ---------------- Phase 2: out = h1 @ Wout^T ----------------
    u64 oacc[4][8];
    #pragma unroll
    for (int p = 0; p < 4; p++)
        #pragma unroll
        for (int j = 0; j < 8; j++) oacc[p][j] = 0ull;

    #pragma unroll 1
    for (int kk = 0; kk < 128; kk += TK) {
        // load Bs[k][n] = Wout[n][kk+k]
        {
            int row = tid >> 1;          // 0..127 (n)
            int kq = (tid & 1) * 8;      // 0 or 8
            float4 v0 = *reinterpret_cast<const float4*>(
                Wout + (size_t)row * 128 + kk + kq);
            float4 v1 = *reinterpret_cast<const float4*>(
                Wout + (size_t)row * 128 + kk + kq + 4);
            Bs[(kq + 0) * LDP + row] = v0.x;
            Bs[(kq + 1) * LDP + row] = v0.y;
            Bs[(kq + 2) * LDP + row] = v0.z;
            Bs[(kq + 3) * LDP + row] = v0.w;
            Bs[(kq + 4) * LDP + row] = v1.x;
            Bs[(kq + 5) * LDP + row] = v1.y;
            Bs[(kq + 6) * LDP + row] = v1.z;
            Bs[(kq + 7) * LDP + row] = v1.w;
        }
        __syncthreads();

        #pragma unroll
        for (int k = 0; k < TK; k++) {
            ulonglong2 a01 = *reinterpret_cast<ulonglong2*>(&Hs[(kk + k) * LDP + m0]);
            ulonglong2 a23 = *reinterpret_cast<ulonglong2*>(&Hs[(kk + k) * LDP + m0 + 4]);
            u64 a2[4] = { a01.x, a01.y, a23.x, a23.y };

            float4 t0 = *reinterpret_cast<float4*>(&Bs[k * LDP + n0]);
            float4 t1 = *reinterpret_cast<float4*>(&Bs[k * LDP + n0 + 4]);
            u64 b2[8] = { pack_dup(t0.x), pack_dup(t0.y),
                          pack_dup(t0.z), pack_dup(t0.w),
                          pack_dup(t1.x), pack_dup(t1.y),
                          pack_dup(t1.z), pack_dup(t1.w) };

            #pragma unroll
            for (int p = 0; p < 4; p++)
                #pragma unroll
                for (int j = 0; j < 8; j++)
                    fma2(oacc[p][j], a2[p], b2[j]);
        }
        __syncthreads();
    }

    // ---- epilogue: out bias, float4 stores ----
    float obias[8];
    #pragma unroll
    for (int j = 0; j < 8; j++) obias[j] = __ldg(bout + n0 + j);
    #pragma unroll
    for (int p = 0; p < 4; p++) {
        float vlo[8], vhi[8];
        #pragma unroll
        for (int j = 0; j < 8; j++) {
            float2 f = *reinterpret_cast<float2*>(&oacc[p][j]);
            vlo[j] = f.x + obias[j];
            vhi[j] = f.y + obias[j];
        }
        int rlo = bm + m0 + 2 * p;
        int rhi = rlo + 1;
        if (rlo < M) {
            *reinterpret_cast<float4*>(C + (size_t)rlo * 128 + n0) =
                make_float4(vlo[0], vlo[1], vlo[2], vlo[3]);
            *reinterpret_cast<float4*>(C + (size_t)rlo * 128 + n0 + 4) =
                make_float4(vlo[4], vlo[5], vlo[6], vlo[7]);
        }
        if (rhi < M) {
            *reinterpret_cast<float4*>(C + (size_t)rhi * 128 + n0) =
                make_float4(vhi[0], vhi[1], vhi[2], vhi[3]);
            *reinterpret_cast<float4*>(C + (size_t)rhi * 128 + n0 + 4) =
                make_float4(vhi[4], vhi[5], vhi[6], vhi[7]);
        }
    }
}

// ---------------------------------------------------------------------------
// Launch: only the h_a branch matters — h_b in the reference is dead code.
// ---------------------------------------------------------------------------
extern "C" void kernel_launch(void* const* d_in, const int* in_sizes, int n_in,
                              void* d_out, int out_size) {
    const float* x_a     = (const float*)d_in[0];
    const int*   edge_ba = (const int*)d_in[3];
    const float* c1_w0_w = (const float*)d_in[10];
    const float* c1_w0_b = (const float*)d_in[11];
    const float* c1_wl_w = (const float*)d_in[12];
    const float* c1_wl_b = (const float*)d_in[13];
    const float* c1_w1_w = (const float*)d_in[14];
    const float* c1_w1_b = (const float*)d_in[15];
    const float* out_w   = (const float*)d_in[16];
    const float* out_b   = (const float*)d_in[17];
    float* out = (float*)d_out;

    float* aggr_p = nullptr;
    cudaGetSymbolAddress((void**)&aggr_p, g_aggr);

    const int egrid = (Ee + 255) / 256;   // 1954
    const int ngrid = NBLK;               // 196

    // CSR build (5 launches)
    zero_cnt_kernel<<<ngrid, 256>>>();
    count_kernel<<<egrid, 256>>>(edge_ba);
    scan1_kernel<<<ngrid, 256>>>();
    scan_fixup_kernel<<<ngrid, 256>>>();
    fill_kernel<<<egrid, 256>>>(edge_ba);

    // Gather-reduce into aggr
    aggregate_kernel<<<(Nn + 7) / 8, 256>>>(x_a);

    // Fused h1 + output GEMM
    const int smem_bytes = (2 * TK * LDP + 128 * LDP) * sizeof(float);  // 84480
    cudaFuncSetAttribute(fused_gemm_kernel,
                         cudaFuncAttributeMaxDynamicSharedMemorySize, smem_bytes);
    const int grid = (Nn + 127) / 128;  // 391 blocks
    fused_gemm_kernel<<<grid, 256, smem_bytes>>>(
        aggr_p, c1_wl_w,
        x_a, c1_w0_w, c1_w1_w,
        c1_wl_b, c1_w0_b, c1_w1_b,
        out_w, out_b,
        out, Nn);
}

// round 5
// speedup vs baseline: 1.1587x; 1.1587x over previous
#include <cuda_runtime.h>

#define Nn 50000
#define Hh 128
#define Ee 500000
#define TK 16
#define LDP 132   // padded pitch for shared tiles
#define NBLK 196  // ceil(Nn/256)

typedef unsigned long long u64;

// Scratch (device globals: no allocation allowed)
__device__ float g_aggr[(size_t)Nn * Hh];
__device__ float g_h1[(size_t)Nn * Hh];
__device__ int   g_head[Nn];   // per-node list head (-1 = empty)
__device__ u64   g_link[Ee];   // (src << 32) | next  (next = 0xFFFFFFFF ends)

// ---------------------------------------------------------------------------
// Linked-list build: head init + one-pass atomicExch chain
// ---------------------------------------------------------------------------
__global__ void init_head_kernel() {
    int i = blockIdx.x * 256 + threadIdx.x;
    if (i < Nn) g_head[i] = -1;
}

__global__ void build_kernel(const int* __restrict__ edge) {
    int e = blockIdx.x * 256 + threadIdx.x;
    if (e < Ee) {
        int dst = __ldg(edge + e);        // edge_index[0][e]
        int src = __ldg(edge + Ee + e);   // edge_index[1][e]
        int prev = atomicExch(&g_head[dst], e);
        g_link[e] = ((u64)(unsigned)src << 32) | (unsigned)prev;
    }
}

// ---------------------------------------------------------------------------
// Gather-reduce: one warp per node walks its list. Each step is ONE dependent
// 8B load (src+next packed); the 512B x-row gathers overlap freely.
// ---------------------------------------------------------------------------
__global__ void aggregate_kernel(const float* __restrict__ x) {
    int n = blockIdx.x * 8 + (threadIdx.x >> 5);
    if (n >= Nn) return;
    int lane = threadIdx.x & 31;
    float4 acc = make_float4(0.f, 0.f, 0.f, 0.f);
    int e = g_head[n];
    while (e != -1) {
        u64 pk = __ldg(g_link + e);
        int src = (int)(pk >> 32);
        e = (int)(unsigned)pk;            // 0xFFFFFFFF -> -1
        float4 v = *reinterpret_cast<const float4*>(x + (size_t)src * Hh + lane * 4);
        acc.x += v.x; acc.y += v.y; acc.z += v.z; acc.w += v.w;
    }
    *reinterpret_cast<float4*>(g_aggr + (size_t)n * Hh + lane * 4) = acc;
}

// ---------------------------------------------------------------------------
// f32x2 packed-FMA helpers
// ---------------------------------------------------------------------------
__device__ __forceinline__ u64 pack_dup(float v) {
    u64 r;
    asm("mov.b64 %0, {%1,%1};" : "=l"(r) : "f"(v));
    return r;
}
__device__ __forceinline__ void fma2(u64& acc, u64 a, u64 b) {
    asm("fma.rn.f32x2 %0, %1, %2, %0;" : "+l"(acc) : "l"(a), "l"(b));
}

// ---------------------------------------------------------------------------
// Tiled SGEMM with packed f32x2 FMAs (R2 version — known good):
//   C[M,128] = act( A0 @ W0^T + (A1 @ (W1a+W1b)^T) + biases )
//   128x128 tile / block, TK=16, 256 threads, 8x8 microtile (paired along m)
// ---------------------------------------------------------------------------
__global__ __launch_bounds__(256, 2) void gemm_kernel(
    const float* __restrict__ A0, const float* __restrict__ W0,
    const float* __restrict__ A1, const float* __restrict__ W1a,
    const float* __restrict__ W1b,
    const float* __restrict__ ba, const float* __restrict__ bb,
    const float* __restrict__ bc,
    float* __restrict__ C, int M, int do_relu)
{
    __shared__ __align__(16) float As[TK * LDP];
    __shared__ __align__(16) float Bs[TK * LDP];

    const int tid = threadIdx.x;
    const int ty = tid >> 4;        // 0..15
    const int tx = tid & 15;        // 0..15
    const int m0 = ty * 8;
    const int n0 = tx * 8;
    const int bm = blockIdx.x * 128;

    // acc2[p][j] = ( C[m0+2p][n0+j], C[m0+2p+1][n0+j] )
    u64 acc2[4][8];
    #pragma unroll
    for (int p = 0; p < 4; p++)
        #pragma unroll
        for (int j = 0; j < 8; j++) acc2[p][j] = 0ull;

    const int nseg = (A1 != nullptr) ? 2 : 1;
    for (int seg = 0; seg < nseg; seg++) {
        const float* A  = seg ? A1 : A0;
        const float* Wa = seg ? W1a : W0;
        const float* Wb = seg ? W1b : nullptr;

        for (int kk = 0; kk < 128; kk += TK) {
            // ---- stage A tile (k-major: As[k][m]) and B tile (Bs[k][n]) ----
            #pragma unroll
            for (int q = 0; q < 2; q++) {
                int l = q * 256 + tid;     // 0..511
                int row = l >> 2;          // 0..127
                int kq = (l & 3) * 4;      // 0,4,8,12

                float4 va = make_float4(0.f, 0.f, 0.f, 0.f);
                if (bm + row < M)
                    va = *reinterpret_cast<const float4*>(
                        A + (size_t)(bm + row) * 128 + kk + kq);
                As[(kq + 0) * LDP + row] = va.x;
                As[(kq + 1) * LDP + row] = va.y;
                As[(kq + 2) * LDP + row] = va.z;
                As[(kq + 3) * LDP + row] = va.w;

                float4 vb = *reinterpret_cast<const float4*>(
                    Wa + (size_t)row * 128 + kk + kq);
                if (Wb) {
                    float4 v2 = *reinterpret_cast<const float4*>(
                        Wb + (size_t)row * 128 + kk + kq);
                    vb.x += v2.x; vb.y += v2.y; vb.z += v2.z; vb.w += v2.w;
                }
                Bs[(kq + 0) * LDP + row] = vb.x;
                Bs[(kq + 1) * LDP + row] = vb.y;
                Bs[(kq + 2) * LDP + row] = vb.z;
                Bs[(kq + 3) * LDP + row] = vb.w;
            }
            __syncthreads();

            // ---- compute: packed pairs along m ----
            #pragma unroll
            for (int k = 0; k < TK; k++) {
                ulonglong2 a01 = *reinterpret_cast<ulonglong2*>(&As[k * LDP + m0]);
                ulonglong2 a23 = *reinterpret_cast<ulonglong2*>(&As[k * LDP + m0 + 4]);
                u64 a2[4] = { a01.x, a01.y, a23.x, a23.y };

                float4 t0 = *reinterpret_cast<float4*>(&Bs[k * LDP + n0]);
                float4 t1 = *reinterpret_cast<float4*>(&Bs[k * LDP + n0 + 4]);
                u64 b2[8] = { pack_dup(t0.x), pack_dup(t0.y),
                              pack_dup(t0.z), pack_dup(t0.w),
                              pack_dup(t1.x), pack_dup(t1.y),
                              pack_dup(t1.z), pack_dup(t1.w) };

                #pragma unroll
                for (int p = 0; p < 4; p++)
                    #pragma unroll
                    for (int j = 0; j < 8; j++)
                        fma2(acc2[p][j], a2[p], b2[j]);
            }
            __syncthreads();
        }
    }

    // ---- epilogue: bias + optional relu, float4 stores (row pairs) ----
    float bias[8];
    #pragma unroll
    for (int j = 0; j < 8; j++) {
        float s = 0.f;
        if (ba) s += __ldg(ba + n0 + j);
        if (bb) s += __ldg(bb + n0 + j);
        if (bc) s += __ldg(bc + n0 + j);
        bias[j] = s;
    }
    #pragma unroll
    for (int p = 0; p < 4; p++) {
        float vlo[8], vhi[8];
        #pragma unroll
        for (int j = 0; j < 8; j++) {
            float2 f = *reinterpret_cast<float2*>(&acc2[p][j]);
            float xlo = f.x + bias[j];
            float xhi = f.y + bias[j];
            vlo[j] = do_relu ? fmaxf(xlo, 0.f) : xlo;
            vhi[j] = do_relu ? fmaxf(xhi, 0.f) : xhi;
        }
        int rlo = bm + m0 + 2 * p;
        int rhi = rlo + 1;
        if (rlo < M) {
            *reinterpret_cast<float4*>(C + (size_t)rlo * 128 + n0) =
                make_float4(vlo[0], vlo[1], vlo[2], vlo[3]);
            *reinterpret_cast<float4*>(C + (size_t)rlo * 128 + n0 + 4) =
                make_float4(vlo[4], vlo[5], vlo[6], vlo[7]);
        }
        if (rhi < M) {
            *reinterpret_cast<float4*>(C + (size_t)rhi * 128 + n0) =
                make_float4(vhi[0], vhi[1], vhi[2], vhi[3]);
            *reinterpret_cast<float4*>(C + (size_t)rhi * 128 + n0 + 4) =
                make_float4(vhi[4], vhi[5], vhi[6], vhi[7]);
        }
    }
}

// ---------------------------------------------------------------------------
// Launch: only the h_a branch matters — h_b in the reference is dead code.
// out = (relu(aggr_ba @ wl.T + x_a @ (w0+w1).T + biases)) @ out_w.T + out_b
// ---------------------------------------------------------------------------
extern "C" void kernel_launch(void* const* d_in, const int* in_sizes, int n_in,
                              void* d_out, int out_size) {
    const float* x_a     = (const float*)d_in[0];
    const int*   edge_ba = (const int*)d_in[3];
    const float* c1_w0_w = (const float*)d_in[10];
    const float* c1_w0_b = (const float*)d_in[11];
    const float* c1_wl_w = (const float*)d_in[12];
    const float* c1_wl_b = (const float*)d_in[13];
    const float* c1_w1_w = (const float*)d_in[14];
    const float* c1_w1_b = (const float*)d_in[15];
    const float* out_w   = (const float*)d_in[16];
    const float* out_b   = (const float*)d_in[17];
    float* out = (float*)d_out;

    float *aggr_p = nullptr, *h1_p = nullptr;
    cudaGetSymbolAddress((void**)&aggr_p, g_aggr);
    cudaGetSymbolAddress((void**)&h1_p, g_h1);

    const int egrid = (Ee + 255) / 256;   // 1954

    // Linked-list build (2 launches)
    init_head_kernel<<<NBLK, 256>>>();
    build_kernel<<<egrid, 256>>>(edge_ba);

    // Gather-reduce into aggr
    aggregate_kernel<<<(Nn + 7) / 8, 256>>>(x_a);

    const int grid = (Nn + 127) / 128;  // 391 blocks

    // h1 = relu(aggr @ wl.T + x_a @ (w0+w1).T + (bl+b0+b1))
    gemm_kernel<<<grid, 256>>>(aggr_p, c1_wl_w,
                               x_a, c1_w0_w, c1_w1_w,
                               c1_wl_b, c1_w0_b, c1_w1_b,
                               h1_p, Nn, 1);

    // out = h1 @ out_w.T + out_b
    gemm_kernel<<<grid, 256>>>(h1_p, out_w,
                               nullptr, nullptr, nullptr,
                               out_b, nullptr, nullptr,
                               out, Nn, 0);
}